// round 14
// baseline (speedup 1.0000x reference)
#include <cuda_runtime.h>
#include <cstdint>
#include <cfloat>

#define INSZ   128
#define OUTSZ  128
#define BATCH  1024
#define GB     256                 // batch elems per group

// smem (floats)
#define KNF    (127 * 128)         // sorted knees [127][128]  (80 real + pad)
#define CFF    (81 * 128 * 2)      // coefs float2 [81][128]
#define REDF   (4 * 16 * 129)      // per-group red [16][129]
#define PRF    (4 * 8 * 17)        // per-group pr  [8][17]
#define SMEMF  (KNF + CFF + REDF + PRF)

// compare-swap of (knee, dα, dβ) triples
#define CSW(p, q) { bool sw_ = knv[p] > knv[q];                               \
    float ta_ = sw_ ? knv[q] : knv[p], tb_ = sw_ ? knv[p] : knv[q];           \
    knv[p] = ta_; knv[q] = tb_;                                               \
    ta_ = sw_ ? da[q] : da[p]; tb_ = sw_ ? da[p] : da[q]; da[p] = ta_; da[q] = tb_; \
    ta_ = sw_ ? db[q] : db[p]; tb_ = sw_ ? db[p] : db[q]; db[p] = ta_; db[q] = tb_; }

// ---------------------------------------------------------------------------
// Full piecewise-linear collapse. One 512-thread CTA per output o; 4 groups
// of 128 threads (thread = input feature i) evaluate disjoint 256-elem batch
// ranges against ONE shared table:
//   f_{i,o}(v) = alpha[c]*v + beta[c],  c = #(knees < v)  (<=80 knees)
// Flat knee layout (sorted by construction): region r intra knees at flat
// idx 9r..9r+7 (clamped into [K_r, K_{r+1}]), boundary knee K_r at 9r-1.
// For v in region r above s intra knees: c = 9r + s -> coef slot 9r+s, where
// coefs are region-locally ABSOLUTE (base + cumulative deltas), so no
// cross-region stitching exists and zero-width pieces are harmless (f is
// continuous). Eval: 7-probe branchless lower_bound + LDS.64 + 1 FMA.
// ---------------------------------------------------------------------------
__global__ void __launch_bounds__(512)
mlpkan_pwl(const float* __restrict__ x,
           const float* __restrict__ W1, const float* __restrict__ b1,
           const float* __restrict__ W2, const float* __restrict__ b2,
           const float* __restrict__ W3, const float* __restrict__ b3,
           float* __restrict__ out) {
    extern __shared__ float sm[];
    float*  kn_sm = sm;                       // [127][128]
    float2* cf_sm = (float2*)(sm + KNF);      // [81][128]
    float*  redA  = sm + KNF + CFF;           // [4][16][129]
    float*  prA   = redA + REDF;              // [4][8][17]

    const int o   = blockIdx.x;
    const int tid = threadIdx.x;
    const int g   = tid >> 7;                 // batch group 0..3
    const int i   = tid & 127;                // input feature
    const int n   = i * OUTSZ + o;            // subnet id
    const int w4  = (tid >> 5) & 3;           // warp within group

    // ---- x prefetch first (overlaps build) ----
    int e[8];
#pragma unroll
    for (int u = 0; u < 8; u++) e[u] = (u + 2 * w4) & 7;
    const float* xp = x + (size_t)g * GB * INSZ + i;
    float vbuf[8];
#pragma unroll
    for (int u = 0; u < 8; u++) vbuf[u] = xp[(size_t)e[u] * INSZ];

    // =========================== build =====================================
    float a[8], c[8], b2v[8], w3v[8], b3s;
    {
        const float4* W1v = (const float4*)(W1 + (size_t)n * 8);
        const float4* b1v = (const float4*)(b1 + (size_t)n * 8);
        float4 t0 = W1v[0], t1 = W1v[1];
        a[0]=t0.x; a[1]=t0.y; a[2]=t0.z; a[3]=t0.w;
        a[4]=t1.x; a[5]=t1.y; a[6]=t1.z; a[7]=t1.w;
        t0 = b1v[0]; t1 = b1v[1];
        c[0]=t0.x; c[1]=t0.y; c[2]=t0.z; c[3]=t0.w;
        c[4]=t1.x; c[5]=t1.y; c[6]=t1.z; c[7]=t1.w;
        const float4* b2q = (const float4*)(b2 + (size_t)n * 8);
        t0 = b2q[0]; t1 = b2q[1];
        b2v[0]=t0.x; b2v[1]=t0.y; b2v[2]=t0.z; b2v[3]=t0.w;
        b2v[4]=t1.x; b2v[5]=t1.y; b2v[6]=t1.z; b2v[7]=t1.w;
        const float4* w3q = (const float4*)(W3 + (size_t)n * 8);
        t0 = w3q[0]; t1 = w3q[1];
        w3v[0]=t0.x; w3v[1]=t0.y; w3v[2]=t0.z; w3v[3]=t0.w;
        w3v[4]=t1.x; w3v[5]=t1.y; w3v[6]=t1.z; w3v[7]=t1.w;
        b3s = b3[n];
    }

    float knee[8];
#pragma unroll
    for (int k = 0; k < 8; k++)
        knee[k] = (a[k] != 0.0f) ? (-c[k] / a[k]) : -FLT_MAX;
    int rank[8];
#pragma unroll
    for (int k = 0; k < 8; k++) {
        int rk = 0;
#pragma unroll
        for (int m = 0; m < 8; m++)
            rk += (knee[m] < knee[k]) || (knee[m] == knee[k] && m < k);
        rank[k] = rk;
    }

    // regions split across groups: g, g+4, g+8
#pragma unroll 1
    for (int r = g; r < 9; r += 4) {
        float Kr = -FLT_MAX, Kn = FLT_MAX;
#pragma unroll
        for (int k = 0; k < 8; k++) {
            if (rank[k] == r - 1) Kr = knee[k];
            if (rank[k] == r)     Kn = knee[k];
        }

        // layer-1 activation factors for this region (R13-proven rule)
        float aa[8], cc[8];
#pragma unroll
        for (int k = 0; k < 8; k++) {
            bool act;
            if (a[k] > 0.0f)      act = (rank[k] < r);
            else if (a[k] < 0.0f) act = (rank[k] >= r);
            else                  act = false;
            aa[k] = act ? a[k] : 0.0f;
            cc[k] = act ? c[k] : 0.0f;
            if (a[k] == 0.0f && c[k] > 0.0f) cc[k] = c[k];
        }

        // layer-2 affine coefs A_j, B_j; then knees + deltas + base
        float al = 0.0f, be = b3s;
        float knv[8], da[8], db[8];
#pragma unroll
        for (int j = 0; j < 8; j++) {
            const float4* W2v = (const float4*)(W2 + (size_t)n * 64 + j * 8);
            float4 r0 = W2v[0], r1 = W2v[1];
            float w2r[8] = {r0.x, r0.y, r0.z, r0.w, r1.x, r1.y, r1.z, r1.w};
            float A = 0.0f, B = b2v[j];
#pragma unroll
            for (int k = 0; k < 8; k++) {
                A = fmaf(w2r[k], aa[k], A);
                B = fmaf(w2r[k], cc[k], B);
            }
            // active at region start (limit from the right of K_r)
            float g0v = A * Kr + B;              // A==0 -> B; Kr=-inf -> ±inf
            bool act0 = (g0v > 0.0f) || (g0v == 0.0f && A > 0.0f);
            if (act0) { al = fmaf(w3v[j], A, al); be = fmaf(w3v[j], B, be); }
            // knee of unit j inside the region?
            float t = -B / A;                    // A==0 -> inf/NaN (invalid)
            bool valid = (A != 0.0f) && (t > Kr) && (t < Kn);
            float sgn = (A > 0.0f) ? 1.0f : -1.0f;
            knv[j] = valid ? t : ((t >= Kn) ? Kn : Kr);  // NaN -> Kr
            da[j]  = valid ? sgn * w3v[j] * A : 0.0f;
            db[j]  = valid ? sgn * w3v[j] * B : 0.0f;
        }

        // sort 8 triples by knee (Batcher odd-even merge, 19 comparators)
        CSW(0,1) CSW(2,3) CSW(4,5) CSW(6,7)
        CSW(0,2) CSW(1,3) CSW(4,6) CSW(5,7)
        CSW(1,2) CSW(5,6)
        CSW(0,4) CSW(1,5) CSW(2,6) CSW(3,7)
        CSW(2,4) CSW(3,5)
        CSW(1,2) CSW(3,4) CSW(5,6)

        // emit knees (flat sorted layout) + absolute cumulative coefs
#pragma unroll
        for (int s = 0; s < 8; s++) kn_sm[(9 * r + s) * 128 + i] = knv[s];
        if (r >= 1) kn_sm[(9 * r - 1) * 128 + i] = Kr;
        float ca = al, cb = be;
        cf_sm[(9 * r) * 128 + i] = make_float2(ca, cb);
#pragma unroll
        for (int s = 0; s < 8; s++) {
            ca += da[s]; cb += db[s];
            cf_sm[(9 * r + s + 1) * 128 + i] = make_float2(ca, cb);
        }
    }
    // pad knees 80..126 with FLT_MAX (>= any clamped knee; search-safe)
    for (int q = 80 + g; q < 127; q += 4) kn_sm[q * 128 + i] = FLT_MAX;
    __syncthreads();

    // ============================ eval =====================================
    float* red = redA + g * (16 * 129);
    float* pr  = prA  + g * (8 * 17);

#pragma unroll 1
    for (int s = 0; s < 16; s++) {            // 16 supersteps of 16 elems
#pragma unroll
        for (int hf = 0; hf < 2; hf++) {
#pragma unroll
            for (int u = 0; u < 8; u++) {
                const int bb = hf * 8 + e[u];
                const int b  = s * 16 + bb;
                float v = vbuf[u];
                vbuf[u] = xp[(size_t)((b + 8) & 255) * INSZ];

                // branchless lower_bound over 127 sorted knees -> piece id
                int pos = 0;
                if (v > kn_sm[(pos + 63) * 128 + i]) pos += 64;
                if (v > kn_sm[(pos + 31) * 128 + i]) pos += 32;
                if (v > kn_sm[(pos + 15) * 128 + i]) pos += 16;
                if (v > kn_sm[(pos +  7) * 128 + i]) pos += 8;
                if (v > kn_sm[(pos +  3) * 128 + i]) pos += 4;
                if (v > kn_sm[(pos +  1) * 128 + i]) pos += 2;
                if (v > kn_sm[(pos     ) * 128 + i]) pos += 1;

                float2 cf = cf_sm[pos * 128 + i];
                red[bb * 129 + i] = fmaf(cf.x, v, cf.y);
            }
        }
        asm volatile("bar.sync %0, %1;" :: "r"(g + 1), "r"(128) : "memory");

        // stage-1: thread (bb = i&15, rq = i>>4) sums 16 i-values of row bb
        {
            const int bb = i & 15, rq = i >> 4;
            const float* rr = &red[bb * 129 + rq * 16];
            float s0 = 0.f, s1 = 0.f, s2 = 0.f, s3 = 0.f;
#pragma unroll
            for (int q = 0; q < 16; q += 4) {
                s0 += rr[q + 0]; s1 += rr[q + 1];
                s2 += rr[q + 2]; s3 += rr[q + 3];
            }
            pr[rq * 17 + bb] = (s0 + s1) + (s2 + s3);
        }
        asm volatile("bar.sync %0, %1;" :: "r"(g + 1), "r"(128) : "memory");

        // stage-2: 16 lanes combine 8 partials + store
        if (i < 16) {
            float r0 = 0.f, r1 = 0.f;
#pragma unroll
            for (int q = 0; q < 8; q += 2) {
                r0 += pr[q * 17 + i];
                r1 += pr[(q + 1) * 17 + i];
            }
            out[(size_t)(g * GB + s * 16 + i) * OUTSZ + o] = r0 + r1;
        }
    }
}

// ---------------------------------------------------------------------------
extern "C" void kernel_launch(void* const* d_in, const int* in_sizes, int n_in,
                              void* d_out, int out_size) {
    const float* x  = (const float*)d_in[0];
    const float* W1 = (const float*)d_in[1];
    const float* b1 = (const float*)d_in[2];
    const float* W2 = (const float*)d_in[3];
    const float* b2 = (const float*)d_in[4];
    const float* W3 = (const float*)d_in[5];
    const float* b3 = (const float*)d_in[6];
    float* out = (float*)d_out;

    static int configured = 0;
    if (!configured) {
        cudaFuncSetAttribute(mlpkan_pwl,
                             cudaFuncAttributeMaxDynamicSharedMemorySize,
                             SMEMF * 4);
        configured = 1;
    }

    mlpkan_pwl<<<OUTSZ, 512, SMEMF * 4>>>(x, W1, b1, W2, b2, W3, b3, out);
}

// round 15
// speedup vs baseline: 1.1976x; 1.1976x over previous
#include <cuda_runtime.h>
#include <cstdint>
#include <cfloat>

#define INSZ   128
#define OUTSZ  128
#define BATCH  1024
#define GB     256                 // batch elems per group

// smem (floats)
#define KN4F   (18 * 128 * 4)      // intra knees [9 regions][2 float4-rows][128]
#define CFF    (81 * 128 * 2)      // coefs float2 [81][128]
#define REDF   (4 * 32 * 129)      // per-group red [32][129]
#define PRF    (4 * 4 * 33)        // per-group pr  [4][33]
#define SMEMF  (KN4F + CFF + REDF + PRF)

// compare-swap of (knee, dα, dβ) triples
#define CSW(p, q) { bool sw_ = knv[p] > knv[q];                               \
    float ta_ = sw_ ? knv[q] : knv[p], tb_ = sw_ ? knv[p] : knv[q];           \
    knv[p] = ta_; knv[q] = tb_;                                               \
    ta_ = sw_ ? da[q] : da[p]; tb_ = sw_ ? da[p] : da[q]; da[p] = ta_; da[q] = tb_; \
    ta_ = sw_ ? db[q] : db[p]; tb_ = sw_ ? db[p] : db[q]; db[p] = ta_; db[q] = tb_; }

// ---------------------------------------------------------------------------
// Full piecewise-linear collapse, 2-level parallel lookup.
//   f_{i,o}(v) = alpha*v + beta on piece (r, s):
//     r = #(layer-1 knees < v)          -- 8 REGISTER compares (sort-free)
//     s = #(region-r intra knees < v)   -- 2 parallel LDS.128 + 8 compares
//   coef slot 9r+s holds region-locally ABSOLUTE (alpha,beta) (base +
//   cumulative sorted deltas), so zero-width / clamped pieces are harmless
//   (f continuous; boundary evals exact from either side).
// Table layouts put lane index i innermost: kn4 bank=4i (LDS.128 phases
// conflict-free for any per-lane r), cf bank=2i (LDS.64 conflict-free).
// One 512-thread CTA per o; 4 groups x 128 threads; group-local barriers.
// ---------------------------------------------------------------------------
__global__ void __launch_bounds__(512)
mlpkan_pwl(const float* __restrict__ x,
           const float* __restrict__ W1, const float* __restrict__ b1,
           const float* __restrict__ W2, const float* __restrict__ b2,
           const float* __restrict__ W3, const float* __restrict__ b3,
           float* __restrict__ out) {
    extern __shared__ float sm[];
    float4* kn4   = (float4*)sm;              // [18][128] float4
    float2* cf_sm = (float2*)(sm + KN4F);     // [81][128] float2
    float*  redA  = sm + KN4F + CFF;          // [4][32][129]
    float*  prA   = redA + REDF;              // [4][4][33]

    const int o   = blockIdx.x;
    const int tid = threadIdx.x;
    const int g   = tid >> 7;                 // batch group 0..3
    const int i   = tid & 127;                // input feature
    const int n   = i * OUTSZ + o;            // subnet id
    const int w4  = (tid >> 5) & 3;           // warp within group

    // ---- x prefetch first (overlaps build) ----
    int e[8];
#pragma unroll
    for (int u = 0; u < 8; u++) e[u] = (u + 2 * w4) & 7;
    const float* xp = x + (size_t)g * GB * INSZ + i;
    float vbuf[8];
#pragma unroll
    for (int u = 0; u < 8; u++) vbuf[u] = xp[(size_t)e[u] * INSZ];

    // =========================== build =====================================
    float a[8], c[8], b2v[8], w3v[8], b3s;
    {
        const float4* W1v = (const float4*)(W1 + (size_t)n * 8);
        const float4* b1v = (const float4*)(b1 + (size_t)n * 8);
        float4 t0 = W1v[0], t1 = W1v[1];
        a[0]=t0.x; a[1]=t0.y; a[2]=t0.z; a[3]=t0.w;
        a[4]=t1.x; a[5]=t1.y; a[6]=t1.z; a[7]=t1.w;
        t0 = b1v[0]; t1 = b1v[1];
        c[0]=t0.x; c[1]=t0.y; c[2]=t0.z; c[3]=t0.w;
        c[4]=t1.x; c[5]=t1.y; c[6]=t1.z; c[7]=t1.w;
        const float4* b2q = (const float4*)(b2 + (size_t)n * 8);
        t0 = b2q[0]; t1 = b2q[1];
        b2v[0]=t0.x; b2v[1]=t0.y; b2v[2]=t0.z; b2v[3]=t0.w;
        b2v[4]=t1.x; b2v[5]=t1.y; b2v[6]=t1.z; b2v[7]=t1.w;
        const float4* w3q = (const float4*)(W3 + (size_t)n * 8);
        t0 = w3q[0]; t1 = w3q[1];
        w3v[0]=t0.x; w3v[1]=t0.y; w3v[2]=t0.z; w3v[3]=t0.w;
        w3v[4]=t1.x; w3v[5]=t1.y; w3v[6]=t1.z; w3v[7]=t1.w;
        b3s = b3[n];
    }

    float knee[8];
#pragma unroll
    for (int k = 0; k < 8; k++)
        knee[k] = (a[k] != 0.0f) ? (-c[k] / a[k]) : -FLT_MAX;
    int rank[8];
#pragma unroll
    for (int k = 0; k < 8; k++) {
        int rk = 0;
#pragma unroll
        for (int m = 0; m < 8; m++)
            rk += (knee[m] < knee[k]) || (knee[m] == knee[k] && m < k);
        rank[k] = rk;
    }

    // regions split across groups: g, g+4, g+8
#pragma unroll 1
    for (int r = g; r < 9; r += 4) {
        float Kr = -FLT_MAX, Kn = FLT_MAX;
#pragma unroll
        for (int k = 0; k < 8; k++) {
            if (rank[k] == r - 1) Kr = knee[k];
            if (rank[k] == r)     Kn = knee[k];
        }

        float aa[8], cc[8];
#pragma unroll
        for (int k = 0; k < 8; k++) {
            bool act;
            if (a[k] > 0.0f)      act = (rank[k] < r);
            else if (a[k] < 0.0f) act = (rank[k] >= r);
            else                  act = false;
            aa[k] = act ? a[k] : 0.0f;
            cc[k] = act ? c[k] : 0.0f;
            if (a[k] == 0.0f && c[k] > 0.0f) cc[k] = c[k];
        }

        float al = 0.0f, be = b3s;
        float knv[8], da[8], db[8];
#pragma unroll
        for (int j = 0; j < 8; j++) {
            const float4* W2v = (const float4*)(W2 + (size_t)n * 64 + j * 8);
            float4 r0 = W2v[0], r1 = W2v[1];
            float w2r[8] = {r0.x, r0.y, r0.z, r0.w, r1.x, r1.y, r1.z, r1.w};
            float A = 0.0f, B = b2v[j];
#pragma unroll
            for (int k = 0; k < 8; k++) {
                A = fmaf(w2r[k], aa[k], A);
                B = fmaf(w2r[k], cc[k], B);
            }
            float g0v = A * Kr + B;
            bool act0 = (g0v > 0.0f) || (g0v == 0.0f && A > 0.0f);
            if (act0) { al = fmaf(w3v[j], A, al); be = fmaf(w3v[j], B, be); }
            float t = -B / A;
            bool valid = (A != 0.0f) && (t > Kr) && (t < Kn);
            float sgn = (A > 0.0f) ? 1.0f : -1.0f;
            knv[j] = valid ? t : ((t >= Kn) ? Kn : Kr);   // NaN -> Kr
            da[j]  = valid ? sgn * w3v[j] * A : 0.0f;
            db[j]  = valid ? sgn * w3v[j] * B : 0.0f;
        }

        // sort 8 triples by knee (Batcher odd-even merge)
        CSW(0,1) CSW(2,3) CSW(4,5) CSW(6,7)
        CSW(0,2) CSW(1,3) CSW(4,6) CSW(5,7)
        CSW(1,2) CSW(5,6)
        CSW(0,4) CSW(1,5) CSW(2,6) CSW(3,7)
        CSW(2,4) CSW(3,5)
        CSW(1,2) CSW(3,4) CSW(5,6)

        // emit sorted intra knees (2 float4 rows) + absolute cumulative coefs
        kn4[(r * 2 + 0) * 128 + i] = make_float4(knv[0], knv[1], knv[2], knv[3]);
        kn4[(r * 2 + 1) * 128 + i] = make_float4(knv[4], knv[5], knv[6], knv[7]);
        float ca = al, cb = be;
        cf_sm[(9 * r) * 128 + i] = make_float2(ca, cb);
#pragma unroll
        for (int s = 0; s < 8; s++) {
            ca += da[s]; cb += db[s];
            cf_sm[(9 * r + s + 1) * 128 + i] = make_float2(ca, cb);
        }
    }
    __syncthreads();

    // ============================ eval =====================================
    float* red = redA + g * (32 * 129);
    float* pr  = prA  + g * (4 * 33);

#pragma unroll 1
    for (int s = 0; s < 8; s++) {             // 8 supersteps of 32 elems
#pragma unroll
        for (int hf = 0; hf < 4; hf++) {
#pragma unroll
            for (int u = 0; u < 8; u++) {
                const int bb = hf * 8 + e[u];
                const int b  = s * 32 + bb;
                float v = vbuf[u];
                vbuf[u] = xp[(size_t)((b + 8) & 255) * INSZ];

                // level 1: region from register knees (sort-free count)
                int r = (v > knee[0]) + (v > knee[1]) + (v > knee[2]) + (v > knee[3])
                      + (v > knee[4]) + (v > knee[5]) + (v > knee[6]) + (v > knee[7]);

                // level 2: two independent LDS.128 + 8 register compares
                const float4* kb = kn4 + (r * 2) * 128 + i;
                float4 k0 = kb[0];
                float4 k1 = kb[128];
                int sc = (v > k0.x) + (v > k0.y) + (v > k0.z) + (v > k0.w)
                       + (v > k1.x) + (v > k1.y) + (v > k1.z) + (v > k1.w);

                float2 cf = cf_sm[(9 * r + sc) * 128 + i];
                red[bb * 129 + i] = fmaf(cf.x, v, cf.y);
            }
        }
        asm volatile("bar.sync %0, %1;" :: "r"(g + 1), "r"(128) : "memory");

        // stage-1: thread (rb = i&31, rq = i>>5) sums 32 i-values of row rb
        {
            const int rb = i & 31, rq = i >> 5;
            const float* rr = &red[rb * 129 + rq * 32];
            float s0 = 0.f, s1 = 0.f, s2 = 0.f, s3 = 0.f;
#pragma unroll
            for (int q = 0; q < 32; q += 4) {
                s0 += rr[q + 0]; s1 += rr[q + 1];
                s2 += rr[q + 2]; s3 += rr[q + 3];
            }
            pr[rq * 33 + rb] = (s0 + s1) + (s2 + s3);
        }
        asm volatile("bar.sync %0, %1;" :: "r"(g + 1), "r"(128) : "memory");

        // stage-2: 32 lanes combine 4 partials + store
        if (i < 32) {
            float rv = (pr[i] + pr[33 + i]) + (pr[66 + i] + pr[99 + i]);
            out[(size_t)(g * GB + s * 32 + i) * OUTSZ + o] = rv;
        }
    }
}

// ---------------------------------------------------------------------------
extern "C" void kernel_launch(void* const* d_in, const int* in_sizes, int n_in,
                              void* d_out, int out_size) {
    const float* x  = (const float*)d_in[0];
    const float* W1 = (const float*)d_in[1];
    const float* b1 = (const float*)d_in[2];
    const float* W2 = (const float*)d_in[3];
    const float* b2 = (const float*)d_in[4];
    const float* W3 = (const float*)d_in[5];
    const float* b3 = (const float*)d_in[6];
    float* out = (float*)d_out;

    static int configured = 0;
    if (!configured) {
        cudaFuncSetAttribute(mlpkan_pwl,
                             cudaFuncAttributeMaxDynamicSharedMemorySize,
                             SMEMF * 4);
        configured = 1;
    }

    mlpkan_pwl<<<OUTSZ, 512, SMEMF * 4>>>(x, W1, b1, W2, b2, W3, b3, out);
}

// round 16
// speedup vs baseline: 1.2386x; 1.0343x over previous
#include <cuda_runtime.h>
#include <cstdint>
#include <cfloat>

#define INSZ   128
#define OUTSZ  128
#define BATCH  1024

// smem floats: krg [128][8] | kn4 [128][27] float4 (12-float region pad) | cf [128][81] float2
#define KRGF   (128 * 8)
#define KN4F   (128 * 27 * 4)
#define CFF    (128 * 81 * 2)
#define SMEMF  (KRGF + KN4F + CFF)      // 35584 floats = 142336 B

__device__ float g_xT[INSZ * BATCH];    // transposed x [i][b]

// compare-swap of (knee, dα, dβ) triples
#define CSW(p, q) { bool sw_ = knv[p] > knv[q];                               \
    float ta_ = sw_ ? knv[q] : knv[p], tb_ = sw_ ? knv[p] : knv[q];           \
    knv[p] = ta_; knv[q] = tb_;                                               \
    ta_ = sw_ ? da[q] : da[p]; tb_ = sw_ ? da[p] : da[q]; da[p] = ta_; da[q] = tb_; \
    ta_ = sw_ ? db[q] : db[p]; tb_ = sw_ ? db[p] : db[q]; db[p] = ta_; db[q] = tb_; }

__device__ __forceinline__ int cnt8(float v, float4 a, float4 b) {
    return (v > a.x) + (v > a.y) + (v > a.z) + (v > a.w)
         + (v > b.x) + (v > b.y) + (v > b.z) + (v > b.w);
}

// ---------------------------------------------------------------------------
// x transpose: x[b][i] -> g_xT[i][b]. 32x32 smem tiles, both sides coalesced.
// ---------------------------------------------------------------------------
__global__ void transpose_x(const float* __restrict__ x) {
    __shared__ float t[32][33];
    const int it = blockIdx.x * 32;       // i tile
    const int bt = blockIdx.y * 32;       // b tile
    const int lx = threadIdx.x, ly = threadIdx.y;
#pragma unroll
    for (int k = 0; k < 32; k += 8)
        t[ly + k][lx] = x[(size_t)(bt + ly + k) * INSZ + it + lx];
    __syncthreads();
#pragma unroll
    for (int k = 0; k < 32; k += 8)
        g_xT[(size_t)(it + ly + k) * BATCH + bt + lx] = t[lx][ly + k];
}

// ---------------------------------------------------------------------------
// Full piecewise-linear collapse, register-accumulated eval.
//   f_{i,o}(v) = alpha*v + beta on piece (r, s):
//     r = #(layer-1 knees < v), s = #(region-r sorted intra knees < v)
//   coef slot 9r+s is region-locally ABSOLUTE -> zero-width pieces harmless.
// One 512-thread CTA per o. Build (R15-validated algebra) -> smem tables.
// Eval: lane = batch elem (2 per thread), LOOP OVER i accumulating in a
// register: no barriers, no reduction smem, 2 stores per thread total.
// ---------------------------------------------------------------------------
__global__ void __launch_bounds__(512)
mlpkan_pwl(const float* __restrict__ W1, const float* __restrict__ b1,
           const float* __restrict__ W2, const float* __restrict__ b2,
           const float* __restrict__ W3, const float* __restrict__ b3,
           float* __restrict__ out) {
    extern __shared__ float sm[];
    float*  krg = sm;                          // [128][8] region knees (unsorted)
    float4* kn4 = (float4*)(sm + KRGF);        // [128][27] intra knees (3/region, pad)
    float2* cf  = (float2*)(sm + KRGF + KN4F); // [128][81] absolute coefs

    const int o   = blockIdx.x;
    const int tid = threadIdx.x;
    const int g   = tid >> 7;                  // build group 0..3
    const int i   = tid & 127;                 // subnet input feature (build)
    const int n   = i * OUTSZ + o;

    // =========================== build =====================================
    float a[8], c[8], b2v[8], w3v[8], b3s;
    {
        const float4* W1v = (const float4*)(W1 + (size_t)n * 8);
        const float4* b1v = (const float4*)(b1 + (size_t)n * 8);
        float4 t0 = W1v[0], t1 = W1v[1];
        a[0]=t0.x; a[1]=t0.y; a[2]=t0.z; a[3]=t0.w;
        a[4]=t1.x; a[5]=t1.y; a[6]=t1.z; a[7]=t1.w;
        t0 = b1v[0]; t1 = b1v[1];
        c[0]=t0.x; c[1]=t0.y; c[2]=t0.z; c[3]=t0.w;
        c[4]=t1.x; c[5]=t1.y; c[6]=t1.z; c[7]=t1.w;
        const float4* b2q = (const float4*)(b2 + (size_t)n * 8);
        t0 = b2q[0]; t1 = b2q[1];
        b2v[0]=t0.x; b2v[1]=t0.y; b2v[2]=t0.z; b2v[3]=t0.w;
        b2v[4]=t1.x; b2v[5]=t1.y; b2v[6]=t1.z; b2v[7]=t1.w;
        const float4* w3q = (const float4*)(W3 + (size_t)n * 8);
        t0 = w3q[0]; t1 = w3q[1];
        w3v[0]=t0.x; w3v[1]=t0.y; w3v[2]=t0.z; w3v[3]=t0.w;
        w3v[4]=t1.x; w3v[5]=t1.y; w3v[6]=t1.z; w3v[7]=t1.w;
        b3s = b3[n];
    }

    float knee[8];
#pragma unroll
    for (int k = 0; k < 8; k++)
        knee[k] = (a[k] != 0.0f) ? (-c[k] / a[k]) : -FLT_MAX;
    int rank[8];
#pragma unroll
    for (int k = 0; k < 8; k++) {
        int rk = 0;
#pragma unroll
        for (int m = 0; m < 8; m++)
            rk += (knee[m] < knee[k]) || (knee[m] == knee[k] && m < k);
        rank[k] = rk;
    }

    if (g == 0) {   // region knees once per i
        ((float4*)(krg + i * 8))[0] = make_float4(knee[0], knee[1], knee[2], knee[3]);
        ((float4*)(krg + i * 8))[1] = make_float4(knee[4], knee[5], knee[6], knee[7]);
    }

    // regions split across groups: g, g+4, g+8
#pragma unroll 1
    for (int r = g; r < 9; r += 4) {
        float Kr = -FLT_MAX, Kn = FLT_MAX;
#pragma unroll
        for (int k = 0; k < 8; k++) {
            if (rank[k] == r - 1) Kr = knee[k];
            if (rank[k] == r)     Kn = knee[k];
        }

        float aa[8], cc[8];
#pragma unroll
        for (int k = 0; k < 8; k++) {
            bool act;
            if (a[k] > 0.0f)      act = (rank[k] < r);
            else if (a[k] < 0.0f) act = (rank[k] >= r);
            else                  act = false;
            aa[k] = act ? a[k] : 0.0f;
            cc[k] = act ? c[k] : 0.0f;
            if (a[k] == 0.0f && c[k] > 0.0f) cc[k] = c[k];
        }

        float al = 0.0f, be = b3s;
        float knv[8], da[8], db[8];
#pragma unroll
        for (int j = 0; j < 8; j++) {
            const float4* W2v = (const float4*)(W2 + (size_t)n * 64 + j * 8);
            float4 r0 = W2v[0], r1 = W2v[1];
            float w2r[8] = {r0.x, r0.y, r0.z, r0.w, r1.x, r1.y, r1.z, r1.w};
            float A = 0.0f, B = b2v[j];
#pragma unroll
            for (int k = 0; k < 8; k++) {
                A = fmaf(w2r[k], aa[k], A);
                B = fmaf(w2r[k], cc[k], B);
            }
            float g0v = A * Kr + B;
            bool act0 = (g0v > 0.0f) || (g0v == 0.0f && A > 0.0f);
            if (act0) { al = fmaf(w3v[j], A, al); be = fmaf(w3v[j], B, be); }
            float t = -B / A;
            bool valid = (A != 0.0f) && (t > Kr) && (t < Kn);
            float sgn = (A > 0.0f) ? 1.0f : -1.0f;
            knv[j] = valid ? t : ((t >= Kn) ? Kn : Kr);   // NaN -> Kr
            da[j]  = valid ? sgn * w3v[j] * A : 0.0f;
            db[j]  = valid ? sgn * w3v[j] * B : 0.0f;
        }

        // sort 8 triples by knee (Batcher odd-even merge)
        CSW(0,1) CSW(2,3) CSW(4,5) CSW(6,7)
        CSW(0,2) CSW(1,3) CSW(4,6) CSW(5,7)
        CSW(1,2) CSW(5,6)
        CSW(0,4) CSW(1,5) CSW(2,6) CSW(3,7)
        CSW(2,4) CSW(3,5)
        CSW(1,2) CSW(3,4) CSW(5,6)

        kn4[i * 27 + r * 3 + 0] = make_float4(knv[0], knv[1], knv[2], knv[3]);
        kn4[i * 27 + r * 3 + 1] = make_float4(knv[4], knv[5], knv[6], knv[7]);
        float ca = al, cb = be;
        cf[i * 81 + 9 * r] = make_float2(ca, cb);
#pragma unroll
        for (int s = 0; s < 8; s++) {
            ca += da[s]; cb += db[s];
            cf[i * 81 + 9 * r + s + 1] = make_float2(ca, cb);
        }
    }
    __syncthreads();

    // ============================ eval =====================================
    const int w = tid >> 5, l = tid & 31;
    const int bA = w * 32 + l;            // first batch elem
    const int bB = 512 + bA;              // second batch elem
    float accA = 0.0f, accB = 0.0f;

    const float* xA = g_xT + bA;
    const float* xB = g_xT + bB;

#pragma unroll 2
    for (int ii = 0; ii < 128; ii++) {
        float vA = xA[ii * BATCH];
        float vB = xB[ii * BATCH];

        const float4* kr = (const float4*)(krg + ii * 8);   // broadcast
        float4 ra = kr[0], rb = kr[1];
        int r0 = cnt8(vA, ra, rb);
        int r1 = cnt8(vB, ra, rb);

        const float4* kA = kn4 + ii * 27 + r0 * 3;
        const float4* kB = kn4 + ii * 27 + r1 * 3;
        float4 sAa = kA[0], sAb = kA[1];
        float4 sBa = kB[0], sBb = kB[1];
        int pA = 9 * r0 + cnt8(vA, sAa, sAb);
        int pB = 9 * r1 + cnt8(vB, sBa, sBb);

        float2 cA = cf[ii * 81 + pA];
        float2 cB = cf[ii * 81 + pB];
        accA += fmaf(cA.x, vA, cA.y);
        accB += fmaf(cB.x, vB, cB.y);
    }

    out[(size_t)bA * OUTSZ + o] = accA;
    out[(size_t)bB * OUTSZ + o] = accB;
}

// ---------------------------------------------------------------------------
extern "C" void kernel_launch(void* const* d_in, const int* in_sizes, int n_in,
                              void* d_out, int out_size) {
    const float* x  = (const float*)d_in[0];
    const float* W1 = (const float*)d_in[1];
    const float* b1 = (const float*)d_in[2];
    const float* W2 = (const float*)d_in[3];
    const float* b2 = (const float*)d_in[4];
    const float* W3 = (const float*)d_in[5];
    const float* b3 = (const float*)d_in[6];
    float* out = (float*)d_out;

    static int configured = 0;
    if (!configured) {
        cudaFuncSetAttribute(mlpkan_pwl,
                             cudaFuncAttributeMaxDynamicSharedMemorySize,
                             SMEMF * 4);
        configured = 1;
    }

    transpose_x<<<dim3(4, 32), dim3(32, 8)>>>(x);
    mlpkan_pwl<<<OUTSZ, 512, SMEMF * 4>>>(W1, b1, W2, b2, W3, b3, out);
}

// round 17
// speedup vs baseline: 1.2681x; 1.0238x over previous
#include <cuda_runtime.h>
#include <cstdint>
#include <cfloat>

#define INSZ   128
#define OUTSZ  128
#define BATCH  1024

// smem floats: krg [128][8] | kn4 [128][27] float4 (3/region, pad) | cf [128][81] float2
#define KRGF   (128 * 8)
#define KN4F   (128 * 27 * 4)
#define CFF    (128 * 81 * 2)
#define SMEMF  (KRGF + KN4F + CFF)      // 35584 floats = 142336 B

__device__ float g_xT[INSZ * BATCH];    // transposed x [i][b]

// compare-swap of (knee, dα, dβ) triples
#define CSW(p, q) { bool sw_ = knv[p] > knv[q];                               \
    float ta_ = sw_ ? knv[q] : knv[p], tb_ = sw_ ? knv[p] : knv[q];           \
    knv[p] = ta_; knv[q] = tb_;                                               \
    ta_ = sw_ ? da[q] : da[p]; tb_ = sw_ ? da[p] : da[q]; da[p] = ta_; da[q] = tb_; \
    ta_ = sw_ ? db[q] : db[p]; tb_ = sw_ ? db[p] : db[q]; db[p] = ta_; db[q] = tb_; }

__device__ __forceinline__ int cnt8(float v, float4 a, float4 b) {
    return (v > a.x) + (v > a.y) + (v > a.z) + (v > a.w)
         + (v > b.x) + (v > b.y) + (v > b.z) + (v > b.w);
}

// ---------------------------------------------------------------------------
// x transpose: x[b][i] -> g_xT[i][b]. 32x32 smem tiles, both sides coalesced.
// ---------------------------------------------------------------------------
__global__ void transpose_x(const float* __restrict__ x) {
    __shared__ float t[32][33];
    const int it = blockIdx.x * 32;
    const int bt = blockIdx.y * 32;
    const int lx = threadIdx.x, ly = threadIdx.y;
#pragma unroll
    for (int k = 0; k < 32; k += 8)
        t[ly + k][lx] = x[(size_t)(bt + ly + k) * INSZ + it + lx];
    __syncthreads();
#pragma unroll
    for (int k = 0; k < 32; k += 8)
        g_xT[(size_t)(it + ly + k) * BATCH + bt + lx] = t[lx][ly + k];
}

// ---------------------------------------------------------------------------
// Full piecewise-linear collapse, register-accumulated eval.
//   f_{i,o}(v) = alpha*v + beta on piece (r, s):
//     r = #(layer-1 knees < v), s = #(region-r sorted intra knees < v)
//   coef slot 9r+s is region-locally ABSOLUTE -> zero-width pieces harmless.
// One 512-thread CTA per o. Eval: lane = batch elem (2 per thread), loop
// over i with register accumulation; xT values prefetched 4 deep so the LDG
// never sits on the lookup chain. No barriers, no reduction smem.
// ---------------------------------------------------------------------------
__global__ void __launch_bounds__(512)
mlpkan_pwl(const float* __restrict__ W1, const float* __restrict__ b1,
           const float* __restrict__ W2, const float* __restrict__ b2,
           const float* __restrict__ W3, const float* __restrict__ b3,
           float* __restrict__ out) {
    extern __shared__ float sm[];
    float*  krg = sm;                          // [128][8] region knees (unsorted)
    float4* kn4 = (float4*)(sm + KRGF);        // [128][27] intra knees
    float2* cf  = (float2*)(sm + KRGF + KN4F); // [128][81] absolute coefs

    const int o   = blockIdx.x;
    const int tid = threadIdx.x;
    const int g   = tid >> 7;                  // build group 0..3
    const int i   = tid & 127;                 // subnet input feature (build)
    const int n   = i * OUTSZ + o;

    // =========================== build =====================================
    float a[8], c[8], b2v[8], w3v[8], b3s;
    {
        const float4* W1v = (const float4*)(W1 + (size_t)n * 8);
        const float4* b1v = (const float4*)(b1 + (size_t)n * 8);
        float4 t0 = W1v[0], t1 = W1v[1];
        a[0]=t0.x; a[1]=t0.y; a[2]=t0.z; a[3]=t0.w;
        a[4]=t1.x; a[5]=t1.y; a[6]=t1.z; a[7]=t1.w;
        t0 = b1v[0]; t1 = b1v[1];
        c[0]=t0.x; c[1]=t0.y; c[2]=t0.z; c[3]=t0.w;
        c[4]=t1.x; c[5]=t1.y; c[6]=t1.z; c[7]=t1.w;
        const float4* b2q = (const float4*)(b2 + (size_t)n * 8);
        t0 = b2q[0]; t1 = b2q[1];
        b2v[0]=t0.x; b2v[1]=t0.y; b2v[2]=t0.z; b2v[3]=t0.w;
        b2v[4]=t1.x; b2v[5]=t1.y; b2v[6]=t1.z; b2v[7]=t1.w;
        const float4* w3q = (const float4*)(W3 + (size_t)n * 8);
        t0 = w3q[0]; t1 = w3q[1];
        w3v[0]=t0.x; w3v[1]=t0.y; w3v[2]=t0.z; w3v[3]=t0.w;
        w3v[4]=t1.x; w3v[5]=t1.y; w3v[6]=t1.z; w3v[7]=t1.w;
        b3s = b3[n];
    }

    float knee[8];
#pragma unroll
    for (int k = 0; k < 8; k++)
        knee[k] = (a[k] != 0.0f) ? (-c[k] / a[k]) : -FLT_MAX;
    int rank[8];
#pragma unroll
    for (int k = 0; k < 8; k++) {
        int rk = 0;
#pragma unroll
        for (int m = 0; m < 8; m++)
            rk += (knee[m] < knee[k]) || (knee[m] == knee[k] && m < k);
        rank[k] = rk;
    }

    if (g == 0) {
        ((float4*)(krg + i * 8))[0] = make_float4(knee[0], knee[1], knee[2], knee[3]);
        ((float4*)(krg + i * 8))[1] = make_float4(knee[4], knee[5], knee[6], knee[7]);
    }

    // regions split across groups: g, g+4, g+8
#pragma unroll 1
    for (int r = g; r < 9; r += 4) {
        float Kr = -FLT_MAX, Kn = FLT_MAX;
#pragma unroll
        for (int k = 0; k < 8; k++) {
            if (rank[k] == r - 1) Kr = knee[k];
            if (rank[k] == r)     Kn = knee[k];
        }

        float aa[8], cc[8];
#pragma unroll
        for (int k = 0; k < 8; k++) {
            bool act;
            if (a[k] > 0.0f)      act = (rank[k] < r);
            else if (a[k] < 0.0f) act = (rank[k] >= r);
            else                  act = false;
            aa[k] = act ? a[k] : 0.0f;
            cc[k] = act ? c[k] : 0.0f;
            if (a[k] == 0.0f && c[k] > 0.0f) cc[k] = c[k];
        }

        float al = 0.0f, be = b3s;
        float knv[8], da[8], db[8];
#pragma unroll
        for (int j = 0; j < 8; j++) {
            const float4* W2v = (const float4*)(W2 + (size_t)n * 64 + j * 8);
            float4 r0 = W2v[0], r1 = W2v[1];
            float w2r[8] = {r0.x, r0.y, r0.z, r0.w, r1.x, r1.y, r1.z, r1.w};
            float A = 0.0f, B = b2v[j];
#pragma unroll
            for (int k = 0; k < 8; k++) {
                A = fmaf(w2r[k], aa[k], A);
                B = fmaf(w2r[k], cc[k], B);
            }
            float g0v = A * Kr + B;
            bool act0 = (g0v > 0.0f) || (g0v == 0.0f && A > 0.0f);
            if (act0) { al = fmaf(w3v[j], A, al); be = fmaf(w3v[j], B, be); }
            float t = -B / A;
            bool valid = (A != 0.0f) && (t > Kr) && (t < Kn);
            float sgn = (A > 0.0f) ? 1.0f : -1.0f;
            knv[j] = valid ? t : ((t >= Kn) ? Kn : Kr);   // NaN -> Kr
            da[j]  = valid ? sgn * w3v[j] * A : 0.0f;
            db[j]  = valid ? sgn * w3v[j] * B : 0.0f;
        }

        CSW(0,1) CSW(2,3) CSW(4,5) CSW(6,7)
        CSW(0,2) CSW(1,3) CSW(4,6) CSW(5,7)
        CSW(1,2) CSW(5,6)
        CSW(0,4) CSW(1,5) CSW(2,6) CSW(3,7)
        CSW(2,4) CSW(3,5)
        CSW(1,2) CSW(3,4) CSW(5,6)

        kn4[i * 27 + r * 3 + 0] = make_float4(knv[0], knv[1], knv[2], knv[3]);
        kn4[i * 27 + r * 3 + 1] = make_float4(knv[4], knv[5], knv[6], knv[7]);
        float ca = al, cb = be;
        cf[i * 81 + 9 * r] = make_float2(ca, cb);
#pragma unroll
        for (int s = 0; s < 8; s++) {
            ca += da[s]; cb += db[s];
            cf[i * 81 + 9 * r + s + 1] = make_float2(ca, cb);
        }
    }
    __syncthreads();

    // ============================ eval =====================================
    const int w = tid >> 5, l = tid & 31;
    const int bA = w * 32 + l;            // first batch elem
    const int bB = 512 + bA;              // second batch elem
    float accA0 = 0.0f, accA1 = 0.0f, accB0 = 0.0f, accB1 = 0.0f;

    const float* xA = g_xT + bA;
    const float* xB = g_xT + bB;

    // depth-4 rolling register prefetch of xT values
    float vbufA[4], vbufB[4];
#pragma unroll
    for (int u = 0; u < 4; u++) {
        vbufA[u] = xA[u * BATCH];
        vbufB[u] = xB[u * BATCH];
    }

#pragma unroll 4
    for (int ii = 0; ii < 128; ii++) {
        const int u = ii & 3;
        float vA = vbufA[u];
        float vB = vbufB[u];
        const int nx = ii + 4;
        if (nx < 128) {                   // prefetch own successor
            vbufA[u] = xA[nx * BATCH];
            vbufB[u] = xB[nx * BATCH];
        }

        const float4* kr = (const float4*)(krg + ii * 8);   // broadcast
        float4 ra = kr[0], rb = kr[1];
        int r0 = cnt8(vA, ra, rb);
        int r1 = cnt8(vB, ra, rb);

        const float4* kA = kn4 + ii * 27 + r0 * 3;
        const float4* kB = kn4 + ii * 27 + r1 * 3;
        float4 sAa = kA[0], sAb = kA[1];
        float4 sBa = kB[0], sBb = kB[1];
        int pA = 9 * r0 + cnt8(vA, sAa, sAb);
        int pB = 9 * r1 + cnt8(vB, sBa, sBb);

        float2 cA = cf[ii * 81 + pA];
        float2 cB = cf[ii * 81 + pB];
        if (ii & 1) {
            accA1 += fmaf(cA.x, vA, cA.y);
            accB1 += fmaf(cB.x, vB, cB.y);
        } else {
            accA0 += fmaf(cA.x, vA, cA.y);
            accB0 += fmaf(cB.x, vB, cB.y);
        }
    }

    out[(size_t)bA * OUTSZ + o] = accA0 + accA1;
    out[(size_t)bB * OUTSZ + o] = accB0 + accB1;
}

// ---------------------------------------------------------------------------
extern "C" void kernel_launch(void* const* d_in, const int* in_sizes, int n_in,
                              void* d_out, int out_size) {
    const float* x  = (const float*)d_in[0];
    const float* W1 = (const float*)d_in[1];
    const float* b1 = (const float*)d_in[2];
    const float* W2 = (const float*)d_in[3];
    const float* b2 = (const float*)d_in[4];
    const float* W3 = (const float*)d_in[5];
    const float* b3 = (const float*)d_in[6];
    float* out = (float*)d_out;

    static int configured = 0;
    if (!configured) {
        cudaFuncSetAttribute(mlpkan_pwl,
                             cudaFuncAttributeMaxDynamicSharedMemorySize,
                             SMEMF * 4);
        configured = 1;
    }

    transpose_x<<<dim3(4, 32), dim3(32, 8)>>>(x);
    mlpkan_pwl<<<OUTSZ, 512, SMEMF * 4>>>(W1, b1, W2, b2, W3, b3, out);
}